// round 15
// baseline (speedup 1.0000x reference)
#include <cuda_runtime.h>
#include <cuda_bf16.h>
#include <cuda_fp16.h>

// ---------------------------------------------------------------------------
// NT-Xent loss, N=8192, D=512. FP8 (e4m3, scale 16) mma.sync m16n8k32 with
// f16 accumulation (2x rate), upper-triangular tiles (S = Z Z^T symmetric).
// Epilogue: exp via fma.rn.f16x2 + ex2.approx.f16x2 on the f16x2 accumulators
// (exponent biased +15; bias removed in the final log; diagonal cancelled
// bitwise-exactly), sums in f32.
// 296 CTAs x 512 threads, 2 CTAs/SM. Hot loop on an instruction diet:
// incremental tile decode (no division), hoisted cp.async addresses,
// compile-time ring slots. Final logsumexp fused via completion ticket.
// ---------------------------------------------------------------------------

#define NN      8192
#define DD      512
#define BHALF   4096
#define NTILES  2080
#define NCTAS   296
#define NTHR    512

#define PSC     0.00390625f               // 1/256
#define INV_TAU 14.285714285714286f
// f16 constants: E = rn16(log2e/0.07/256) = 0x2D27, C = rn16(15-20.60993) = 0xC59C
#define E2U     0x2D272D27u
#define NC2U    0xC59CC59Cu
// final log correction: ln2 * (20.6099291555662 - 5.609375)
#define LOGC    10.3975918f

#define A_BYTES  65536       // 128 rows x 512 B (4 chunks x 16 KB)
#define B_OFF    65536
#define B_BYTES  16384       // one B chunk: 128 rows x 128 B
#define SMEM_BYTES (A_BYTES + 2*B_BYTES + 1024)

__device__ __align__(128) unsigned char g_z[(size_t)NN * DD];   // e4m3, x16
__device__ float g_rowsum[NN];
__device__ float g_pos[NN];
__device__ unsigned g_done;

// ------------------------------- helpers -----------------------------------
__device__ __forceinline__ unsigned smem_u32(const void* p) {
    unsigned a;
    asm("{ .reg .u64 t; cvta.to.shared.u64 t, %1; cvt.u32.u64 %0, t; }"
        : "=r"(a) : "l"(p));
    return a;
}
__device__ __forceinline__ unsigned swz(unsigned off) {
    return off ^ ((off >> 3) & 0x70);
}
__device__ __forceinline__ void cp16(unsigned dst, const void* src) {
    asm volatile("cp.async.cg.shared.global [%0], [%1], 16;"
                 :: "r"(dst), "l"(src) : "memory");
}
#define CP_COMMIT() asm volatile("cp.async.commit_group;" ::: "memory")
#define CP_WAIT(n)  asm volatile("cp.async.wait_group %0;" :: "n"(n) : "memory")

__device__ __forceinline__ void ldsm_x4(unsigned* r, unsigned addr) {
    asm volatile("ldmatrix.sync.aligned.m8n8.x4.shared.b16 {%0,%1,%2,%3}, [%4];"
                 : "=r"(r[0]), "=r"(r[1]), "=r"(r[2]), "=r"(r[3]) : "r"(addr));
}
// fp8 mma, f16 accumulator (c0: rows lane>>2, cols 2*(lane&3)+{0,1}; c1: row+8)
__device__ __forceinline__ void mma_fp8h(unsigned* c, const unsigned* a,
                                         unsigned b0, unsigned b1) {
    asm volatile(
        "mma.sync.aligned.m16n8k32.row.col.f16.e4m3.e4m3.f16 "
        "{%0,%1}, {%2,%3,%4,%5}, {%6,%7}, {%0,%1};"
        : "+r"(c[0]), "+r"(c[1])
        : "r"(a[0]), "r"(a[1]), "r"(a[2]), "r"(a[3]), "r"(b0), "r"(b1));
}
__device__ __forceinline__ unsigned hfma2u(unsigned a, unsigned b, unsigned c) {
    unsigned d; asm("fma.rn.f16x2 %0,%1,%2,%3;" : "=r"(d) : "r"(a), "r"(b), "r"(c));
    return d;
}
__device__ __forceinline__ unsigned h2ex2(unsigned a) {
    unsigned d; asm("ex2.approx.f16x2 %0,%1;" : "=r"(d) : "r"(a));
    return d;
}
__device__ __forceinline__ float2 h2f2(unsigned a) {
    __half2 h = *(__half2*)&a;
    return __half22float2(h);
}
__device__ __forceinline__ unsigned short cvt2_e4m3(float lo, float hi) {
    unsigned short r;
    asm("cvt.rn.satfinite.e4m3x2.f32 %0, %1, %2;" : "=h"(r) : "f"(hi), "f"(lo));
    return r;
}

// ------------------------- kernel 1: normalize -> fp8 ----------------------
__global__ __launch_bounds__(256) void ntx_normalize(const float* __restrict__ anchor,
                                                     const float* __restrict__ positive) {
    int gt = blockIdx.x * 256 + threadIdx.x;
    if (gt < NN) g_rowsum[gt] = 0.f;          // graph-replay safe re-init
    if (gt == 0) g_done = 0u;

    int row  = blockIdx.x * 8 + (threadIdx.x >> 5);
    int lane = threadIdx.x & 31;
    const float* src = (row < BHALF) ? (anchor + (size_t)row * DD)
                                     : (positive + (size_t)(row - BHALF) * DD);
    const float4* s4 = (const float4*)src;
    float4 v[4];
    float ss = 0.f;
#pragma unroll
    for (int q = 0; q < 4; q++) {
        v[q] = s4[lane + 32 * q];
        ss += v[q].x * v[q].x + v[q].y * v[q].y + v[q].z * v[q].z + v[q].w * v[q].w;
    }
#pragma unroll
    for (int o = 16; o > 0; o >>= 1) ss += __shfl_xor_sync(0xFFFFFFFFu, ss, o);
    float s16 = 16.0f / fmaxf(sqrtf(ss), 1e-8f);

    unsigned* zp = (unsigned*)(g_z + (size_t)row * DD);
#pragma unroll
    for (int q = 0; q < 4; q++) {
        unsigned lo = cvt2_e4m3(v[q].x * s16, v[q].y * s16);
        unsigned hi = cvt2_e4m3(v[q].z * s16, v[q].w * s16);
        zp[lane + 32 * q] = lo | (hi << 16);
    }
}

// ------------------------- kernel 2: upper-tri GEMM + exp-reduce -----------
__global__ __launch_bounds__(NTHR, 2) void ntx_main(float* __restrict__ out) {
    extern __shared__ char smem_raw[];
    unsigned raw  = smem_u32(smem_raw);
    unsigned base = (raw + 1023u) & ~1023u;
    char* sp      = smem_raw + (base - raw);
    unsigned A  = base;
    unsigned Bb = base + B_OFF;

    int tid  = threadIdx.x;
    int wid  = tid >> 5, lane = tid & 31;
    int warpM = wid & 3, warpN = wid >> 2;     // 4 x 4 warp grid, tile 32x32
    int qrow = lane >> 2;

    int c  = blockIdx.x;
    int t0 = (c * NTILES) / NCTAS;
    int t1 = ((c + 1) * NTILES) / NCTAS;

    // --- per-thread B-load constants (rows tid>>3 and +64, 16B seg tid&7) ---
    int rB  = tid >> 3;
    int c8B = (tid & 7) << 4;
    unsigned dstoff0 = swz((unsigned)(rB * 128 + c8B));
    unsigned dstoff1 = swz((unsigned)((rB + 64) * 128 + c8B));
    size_t   srcoff0 = ((size_t)rB << 9) + (size_t)c8B;
    size_t   srcoff1 = srcoff0 + ((size_t)64 << 9);

    // --- compact ldmatrix addressing ---
    int sel = lane >> 3, lr = lane & 7;
    unsigned cbx[4];
#pragma unroll
    for (int ks = 0; ks < 4; ks++)
        cbx[ks] = ((unsigned)(ks * 32 + ((sel >> 1) << 4))) ^ ((unsigned)lr << 4);
    unsigned arowb[2];
#pragma unroll
    for (int mf = 0; mf < 2; mf++)
        arowb[mf] = (unsigned)((warpM * 32 + mf * 16 + ((sel & 1) << 3) + lr) * 128);
    unsigned browb[2];
#pragma unroll
    for (int p2 = 0; p2 < 2; p2++)
        browb[p2] = (unsigned)((warpN * 32 + p2 * 16 + ((sel & 1) << 3) + lr) * 128);

    // --- incremental tile decode state ---
    int p = t0 / 65;                           // the ONLY division (once)
    int l = t0 - p * 65;

    // prologue: issue chunk 0 of tile t0 into slot 0
    {
        int n1 = 64 - p;
        int J0 = (l < n1) ? (p + l) : (63 - p + (l - n1));
        const char* zJ = (const char*)g_z + ((size_t)J0 << 16);
        cp16(Bb + dstoff0, zJ + srcoff0);
        cp16(Bb + dstoff1, zJ + srcoff1);
        CP_COMMIT();
    }

    unsigned acc[2][4][2];                     // f16x2 accumulators (32x32 tile)
    float rsum[2][2] = {{0.f, 0.f}, {0.f, 0.f}};
    int curI = -1;

    for (int t = t0; t < t1; t++) {
        // decode current tile from (p, l)
        int n1 = 64 - p;
        int I = (l < n1) ? p : (63 - p);
        int J = (l < n1) ? (p + l) : (I + (l - n1));
        int rowbase = I << 7, colbase = J << 7;
        // decode next tile (incremental)
        int pn = p, ln = l + 1;
        if (ln == 65) { ln = 0; pn++; }
        int n1n = 64 - pn;
        int Jn = (ln < n1n) ? (pn + ln) : (63 - pn + (ln - n1n));
        bool nextvalid = (t + 1 < t1);

        const char* zJ  = (const char*)g_z + ((size_t)J  << 16);
        const char* zJn = (const char*)g_z + ((size_t)Jn << 16);

        if (I != curI) {
            if (curI >= 0) {
#pragma unroll
                for (int mf = 0; mf < 2; mf++)
#pragma unroll
                    for (int h = 0; h < 2; h++) {
                        float v = rsum[mf][h];
                        v += __shfl_xor_sync(0xFFFFFFFFu, v, 1);
                        v += __shfl_xor_sync(0xFFFFFFFFu, v, 2);
                        if ((lane & 3) == 0)
                            atomicAdd(&g_rowsum[(curI << 7) + warpM * 32 + mf * 16 + h * 8 + qrow], v);
                        rsum[mf][h] = 0.f;
                    }
            }
            __syncthreads();                   // all readers of old A done
#pragma unroll
            for (int it = 0; it < 8; it++) {
                int x = tid + it * NTHR;
                int r = x >> 5, u = x & 31, ck = u >> 3, c8 = u & 7;
                const uint4* src = (const uint4*)(g_z + ((size_t)(rowbase + r) << 9)
                                                  + ck * 128 + c8 * 16);
                *(uint4*)(sp + ck * 16384 + swz((unsigned)(r * 128 + c8 * 16))) = *src;
            }
            __syncthreads();
            curI = I;
        }

#pragma unroll
        for (int mf = 0; mf < 2; mf++)
#pragma unroll
            for (int nf = 0; nf < 4; nf++) {
                acc[mf][nf][0] = 0u;
                acc[mf][nf][1] = 0u;
            }

#pragma unroll
        for (int k = 0; k < 4; k++) {
            CP_WAIT(0);                        // chunk k of this tile landed
            __syncthreads();
            // issue chunk k+1 into slot (k+1)&1 (overwrites chunk k-1's slot,
            // whose readers all finished before the barrier just crossed)
            if (k < 3) {
                const char* s = zJ + (k + 1) * 128;
                unsigned d = Bb + (((k + 1) & 1) ? B_BYTES : 0);
                cp16(d + dstoff0, s + srcoff0);
                cp16(d + dstoff1, s + srcoff1);
            } else if (nextvalid) {            // chunk 0 of next tile -> slot 0
                cp16(Bb + dstoff0, zJn + srcoff0);
                cp16(Bb + dstoff1, zJn + srcoff1);
            }
            CP_COMMIT();

            unsigned Ac = A + k * 16384;
            unsigned Bc = Bb + ((k & 1) ? B_BYTES : 0);
#pragma unroll
            for (int ks = 0; ks < 4; ks++) {
                unsigned afr[2][4];
                ldsm_x4(afr[0], Ac + arowb[0] + cbx[ks]);
                ldsm_x4(afr[1], Ac + arowb[1] + cbx[ks]);
                unsigned bfr[2][4];
                ldsm_x4(bfr[0], Bc + browb[0] + cbx[ks]);
                ldsm_x4(bfr[1], Bc + browb[1] + cbx[ks]);
#pragma unroll
                for (int mf = 0; mf < 2; mf++)
#pragma unroll
                    for (int nf = 0; nf < 4; nf++)
                        mma_fp8h(acc[mf][nf], afr[mf],
                                 bfr[nf >> 1][nf & 1],
                                 bfr[nf >> 1][2 + (nf & 1)]);
            }
        }

        // ---- epilogue: f16x2 fma+ex2 (bias +15), f32 sums ----
        bool isdiag = (J == I);
        bool ispos  = (J == I + 32);

        if (isdiag | ispos) {
#pragma unroll
            for (int mf = 0; mf < 2; mf++)
#pragma unroll
                for (int h = 0; h < 2; h++) {
                    int rloc = warpM * 32 + mf * 16 + h * 8 + qrow;
                    int cc = rloc - warpN * 32;
                    if (cc >= 0 && cc < 32 && (((cc >> 1) & 3) == (lane & 3))) {
                        unsigned hp = acc[mf][cc >> 3][h];
                        if (isdiag) {
                            // identical f16 recompute -> bitwise-exact cancel
                            float2 fe = h2f2(h2ex2(hfma2u(hp, E2U, NC2U)));
                            rsum[mf][h] -= (cc & 1) ? fe.y : fe.x;
                        }
                        if (ispos) {
                            __half2 hv = *(__half2*)&hp;
                            float v = (cc & 1) ? __high2float(hv) : __low2float(hv);
                            g_pos[rowbase + rloc] = v * PSC;
                            g_pos[rowbase + rloc + BHALF] = v * PSC;
                        }
                    }
                }
        }

        float colp[8];
#pragma unroll
        for (int q = 0; q < 8; q++) colp[q] = 0.f;
#pragma unroll
        for (int mf = 0; mf < 2; mf++) {
            float slo = 0.f, shi = 0.f;
#pragma unroll
            for (int nf = 0; nf < 4; nf++) {
                unsigned eh0 = h2ex2(hfma2u(acc[mf][nf][0], E2U, NC2U));
                unsigned eh1 = h2ex2(hfma2u(acc[mf][nf][1], E2U, NC2U));
                float2 f01 = h2f2(eh0);
                float2 f23 = h2f2(eh1);
                slo += f01.x + f01.y;
                shi += f23.x + f23.y;
                colp[nf * 2]     += f01.x + f23.x;
                colp[nf * 2 + 1] += f01.y + f23.y;
            }
            rsum[mf][0] += slo;
            rsum[mf][1] += shi;
        }

        if (!isdiag) {
#pragma unroll
            for (int q = 0; q < 8; q++) {
                float v = colp[q];
                v += __shfl_xor_sync(0xFFFFFFFFu, v, 4);
                v += __shfl_xor_sync(0xFFFFFFFFu, v, 8);
                v += __shfl_xor_sync(0xFFFFFFFFu, v, 16);
                if (lane < 4) {
                    int ccol = (q >> 1) * 8 + 2 * lane + (q & 1);
                    atomicAdd(&g_rowsum[colbase + warpN * 32 + ccol], v);
                }
            }
        }

        p = pn; l = ln;                        // advance incremental decode
    }

    // final row flush
#pragma unroll
    for (int mf = 0; mf < 2; mf++)
#pragma unroll
        for (int h = 0; h < 2; h++) {
            float v = rsum[mf][h];
            v += __shfl_xor_sync(0xFFFFFFFFu, v, 1);
            v += __shfl_xor_sync(0xFFFFFFFFu, v, 2);
            if ((lane & 3) == 0 && curI >= 0)
                atomicAdd(&g_rowsum[(curI << 7) + warpM * 32 + mf * 16 + h * 8 + qrow], v);
        }

    // ---- completion ticket: last CTA computes the loss ----
    __threadfence();
    __syncthreads();
    __shared__ unsigned ticket;
    if (tid == 0) ticket = atomicAdd(&g_done, 1u);
    __syncthreads();
    if (ticket == NCTAS - 1) {
        float local_s = 0.f;
        for (int r = tid; r < NN; r += NTHR)
            local_s += (1.0f - g_pos[r]) * INV_TAU + __logf(g_rowsum[r]) - LOGC;
#pragma unroll
        for (int o = 16; o > 0; o >>= 1) local_s += __shfl_xor_sync(0xFFFFFFFFu, local_s, o);
        __shared__ float red[16];
        if (lane == 0) red[wid] = local_s;
        __syncthreads();
        if (tid < 16) {
            float v = red[tid];
#pragma unroll
            for (int o = 8; o > 0; o >>= 1) v += __shfl_xor_sync(0xFFFFu, v, o);
            if (tid == 0) out[0] = v * (1.0f / (float)NN);
        }
    }
}

// ---------------------------------------------------------------------------
extern "C" void kernel_launch(void* const* d_in, const int* in_sizes, int n_in,
                              void* d_out, int out_size) {
    (void)in_sizes; (void)n_in; (void)out_size;
    const float* anchor   = (const float*)d_in[0];
    const float* positive = (const float*)d_in[1];

    cudaFuncSetAttribute(ntx_main, cudaFuncAttributeMaxDynamicSharedMemorySize,
                         SMEM_BYTES);

    ntx_normalize<<<NN / 8, 256>>>(anchor, positive);
    ntx_main<<<NCTAS, NTHR, SMEM_BYTES>>>((float*)d_out);
}

// round 16
// speedup vs baseline: 1.0310x; 1.0310x over previous
#include <cuda_runtime.h>
#include <cuda_bf16.h>
#include <cuda_fp16.h>

// ---------------------------------------------------------------------------
// NT-Xent loss, N=8192, D=512 — single fused kernel.
// Phase 0: normalize rows -> e4m3 (x16), zero rowsums, software grid barrier
//          (all 296 CTAs are co-resident: 2/SM x 148 SMs).
// Phase 1: FP8 mma.sync m16n8k32 with f16 accumulation (2x rate),
//          upper-triangular 128x128 tiles of S = Z Z^T (symmetric):
//          tile (I,J), J>I contributes exp-row-sums to block I and
//          exp-col-sums to block J.
// Epilogue: exp via fma.rn.f16x2 + ex2.approx.f16x2 on the f16x2 accumulators
//          (exponent biased +15; bias removed in the final log; diagonal
//          cancelled bitwise-exactly), sums in f32.
// Phase 2: completion-ticket CTA computes the mean loss and resets counters.
// ---------------------------------------------------------------------------

#define NN      8192
#define DD      512
#define BHALF   4096
#define NCHUNK  4            // 512 fp8 bytes / 128-byte chunk
#define NTILES  2080
#define NCTAS   296
#define NTHR    512
#define NWARPS  (NCTAS * 16) // 4736 total warps

#define PSC     0.00390625f               // 1/256
#define INV_TAU 14.285714285714286f
// f16 constants: E = rn16(log2e/0.07/256) = 0x2D27, C = rn16(15-20.60993) = 0xC59C
#define E2U     0x2D272D27u
#define NC2U    0xC59CC59Cu
// final log correction: ln2 * (20.6099291555662 - 5.609375)
#define LOGC    10.3975918f

#define A_BYTES  65536       // 128 rows x 512 B (4 chunks x 16 KB)
#define B_OFF    65536
#define B_BYTES  16384       // one B chunk: 128 rows x 128 B
#define SMEM_BYTES (A_BYTES + 2*B_BYTES + 1024)

__device__ __align__(128) unsigned char g_z[(size_t)NN * DD];   // e4m3, x16
__device__ float g_rowsum[NN];
__device__ float g_pos[NN];
__device__ unsigned g_bar;    // phase-0 grid barrier (reset at end)
__device__ unsigned g_done;   // completion ticket     (reset at end)

// ------------------------------- helpers -----------------------------------
__device__ __forceinline__ unsigned smem_u32(const void* p) {
    unsigned a;
    asm("{ .reg .u64 t; cvta.to.shared.u64 t, %1; cvt.u32.u64 %0, t; }"
        : "=r"(a) : "l"(p));
    return a;
}
__device__ __forceinline__ unsigned swz(unsigned off) {
    return off ^ ((off >> 3) & 0x70);
}
__device__ __forceinline__ void cp16(unsigned dst, const void* src) {
    asm volatile("cp.async.cg.shared.global [%0], [%1], 16;"
                 :: "r"(dst), "l"(src) : "memory");
}
#define CP_COMMIT() asm volatile("cp.async.commit_group;" ::: "memory")
#define CP_WAIT(n)  asm volatile("cp.async.wait_group %0;" :: "n"(n) : "memory")

__device__ __forceinline__ void ldsm_x4(unsigned* r, unsigned addr) {
    asm volatile("ldmatrix.sync.aligned.m8n8.x4.shared.b16 {%0,%1,%2,%3}, [%4];"
                 : "=r"(r[0]), "=r"(r[1]), "=r"(r[2]), "=r"(r[3]) : "r"(addr));
}
// fp8 mma, f16 accumulator (c0: rows lane>>2, cols 2*(lane&3)+{0,1}; c1: row+8)
__device__ __forceinline__ void mma_fp8h(unsigned* c, const unsigned* a,
                                         unsigned b0, unsigned b1) {
    asm volatile(
        "mma.sync.aligned.m16n8k32.row.col.f16.e4m3.e4m3.f16 "
        "{%0,%1}, {%2,%3,%4,%5}, {%6,%7}, {%0,%1};"
        : "+r"(c[0]), "+r"(c[1])
        : "r"(a[0]), "r"(a[1]), "r"(a[2]), "r"(a[3]), "r"(b0), "r"(b1));
}
__device__ __forceinline__ unsigned hfma2u(unsigned a, unsigned b, unsigned c) {
    unsigned d; asm("fma.rn.f16x2 %0,%1,%2,%3;" : "=r"(d) : "r"(a), "r"(b), "r"(c));
    return d;
}
__device__ __forceinline__ unsigned h2ex2(unsigned a) {
    unsigned d; asm("ex2.approx.f16x2 %0,%1;" : "=r"(d) : "r"(a));
    return d;
}
__device__ __forceinline__ float2 h2f2(unsigned a) {
    __half2 h = *(__half2*)&a;
    return __half22float2(h);
}
__device__ __forceinline__ unsigned short cvt2_e4m3(float lo, float hi) {
    unsigned short r;
    asm("cvt.rn.satfinite.e4m3x2.f32 %0, %1, %2;" : "=h"(r) : "f"(hi), "f"(lo));
    return r;
}

// decode flattened tile index -> (I, J)
__device__ __forceinline__ void tile_decode(int t, int& I, int& J) {
    int p = t / 65;
    int l = t - p * 65;
    int n1 = 64 - p;
    if (l < n1) { I = p;      J = p + l; }
    else        { I = 63 - p; J = I + (l - n1); }
}

// ------------------------- B-chunk issue (ring depth 2) --------------------
__device__ __forceinline__ void issueB(unsigned bbase, int colbase, int k, int tid) {
#pragma unroll
    for (int it = 0; it < 2; it++) {
        int idx = tid + it * NTHR;
        int r = idx >> 3, c8 = idx & 7;
        const void* src = g_z + ((size_t)(colbase + r) << 9) + k * 128 + c8 * 16;
        cp16(bbase + swz((unsigned)(r * 128 + c8 * 16)), src);
    }
}
__device__ __forceinline__ void issue_chunk(unsigned Bb, int t0, int t1, int m, int tid) {
    int tt = t0 + (m >> 2);
    if (tt < t1) {
        int I2, J2;
        tile_decode(tt, I2, J2);
        issueB(Bb + (unsigned)(m & 1) * B_BYTES, J2 << 7, m & 3, tid);
    }
    CP_COMMIT();
}

// --------------------------- the fused kernel ------------------------------
__global__ __launch_bounds__(NTHR, 2) void ntx_main(float* __restrict__ out,
                                                    const float* __restrict__ anchor,
                                                    const float* __restrict__ positive) {
    extern __shared__ char smem_raw[];
    unsigned raw  = smem_u32(smem_raw);
    unsigned base = (raw + 1023u) & ~1023u;
    char* sp      = smem_raw + (base - raw);
    unsigned A  = base;
    unsigned Bb = base + B_OFF;

    int tid  = threadIdx.x;
    int wid  = tid >> 5, lane = tid & 31;
    int warpM = wid & 3, warpN = wid >> 2;     // 4 x 4 warp grid, tile 32x32
    int qrow = lane >> 2;
    int c  = blockIdx.x;

    // ================= phase 0: normalize -> fp8 + zero rowsums ============
    {
        int gz = c * NTHR + tid;
        if (gz < NN) g_rowsum[gz] = 0.f;

        int gw = c * 16 + wid;                 // global warp id, 1 row per warp
        for (int row = gw; row < NN; row += NWARPS) {
            const float* src = (row < BHALF) ? (anchor + (size_t)row * DD)
                                             : (positive + (size_t)(row - BHALF) * DD);
            const float4* s4 = (const float4*)src;
            float4 v[4];
            float ss = 0.f;
#pragma unroll
            for (int q = 0; q < 4; q++) {
                v[q] = s4[lane + 32 * q];
                ss += v[q].x * v[q].x + v[q].y * v[q].y + v[q].z * v[q].z + v[q].w * v[q].w;
            }
#pragma unroll
            for (int o = 16; o > 0; o >>= 1) ss += __shfl_xor_sync(0xFFFFFFFFu, ss, o);
            float s16 = 16.0f / fmaxf(sqrtf(ss), 1e-8f);

            unsigned* zp = (unsigned*)(g_z + (size_t)row * DD);
#pragma unroll
            for (int q = 0; q < 4; q++) {
                unsigned lo = cvt2_e4m3(v[q].x * s16, v[q].y * s16);
                unsigned hi = cvt2_e4m3(v[q].z * s16, v[q].w * s16);
                zp[lane + 32 * q] = lo | (hi << 16);
            }
        }

        // software grid barrier (all NCTAS CTAs are co-resident)
        __threadfence();
        __syncthreads();
        if (tid == 0) {
            atomicAdd(&g_bar, 1u);
            while (atomicAdd(&g_bar, 0u) < NCTAS) {}
        }
        __syncthreads();
        __threadfence();
    }

    // ================= phase 1: upper-tri GEMM + exp-reduce ================
    int t0 = (c * NTILES) / NCTAS;
    int t1 = ((c + 1) * NTILES) / NCTAS;

    // compact ldmatrix addressing
    int sel = lane >> 3, lr = lane & 7;
    unsigned cbx[4];
#pragma unroll
    for (int ks = 0; ks < 4; ks++)
        cbx[ks] = ((unsigned)(ks * 32 + ((sel >> 1) << 4))) ^ ((unsigned)lr << 4);
    unsigned arowb[2];
#pragma unroll
    for (int mf = 0; mf < 2; mf++)
        arowb[mf] = (unsigned)((warpM * 32 + mf * 16 + ((sel & 1) << 3) + lr) * 128);
    unsigned browb[2];
#pragma unroll
    for (int p2 = 0; p2 < 2; p2++)
        browb[p2] = (unsigned)((warpN * 32 + p2 * 16 + ((sel & 1) << 3) + lr) * 128);

    issue_chunk(Bb, t0, t1, 0, tid);

    unsigned acc[2][4][2];                     // f16x2 accumulators (32x32 tile)
    float rsum[2][2] = {{0.f, 0.f}, {0.f, 0.f}};
    int curI = -1;
    int cm = 0;

    for (int t = t0; t < t1; t++) {
        int I, J;
        tile_decode(t, I, J);
        int rowbase = I << 7, colbase = J << 7;

        if (I != curI) {
            if (curI >= 0) {
#pragma unroll
                for (int mf = 0; mf < 2; mf++)
#pragma unroll
                    for (int h = 0; h < 2; h++) {
                        float v = rsum[mf][h];
                        v += __shfl_xor_sync(0xFFFFFFFFu, v, 1);
                        v += __shfl_xor_sync(0xFFFFFFFFu, v, 2);
                        if ((lane & 3) == 0)
                            atomicAdd(&g_rowsum[(curI << 7) + warpM * 32 + mf * 16 + h * 8 + qrow], v);
                        rsum[mf][h] = 0.f;
                    }
            }
            __syncthreads();                   // all readers of old A done
#pragma unroll
            for (int it = 0; it < 8; it++) {
                int x = tid + it * NTHR;
                int r = x >> 5, u = x & 31, ck = u >> 3, c8 = u & 7;
                const uint4* src = (const uint4*)(g_z + ((size_t)(rowbase + r) << 9)
                                                  + ck * 128 + c8 * 16);
                *(uint4*)(sp + ck * 16384 + swz((unsigned)(r * 128 + c8 * 16))) = *src;
            }
            __syncthreads();
            curI = I;
        }

#pragma unroll
        for (int mf = 0; mf < 2; mf++)
#pragma unroll
            for (int nf = 0; nf < 4; nf++) {
                acc[mf][nf][0] = 0u;
                acc[mf][nf][1] = 0u;
            }

#pragma unroll
        for (int k = 0; k < NCHUNK; k++) {
            CP_WAIT(0);
            __syncthreads();
            issue_chunk(Bb, t0, t1, cm + 1, tid);

            unsigned Ac = A + k * 16384;
            unsigned Bc = Bb + (unsigned)(cm & 1) * B_BYTES;
#pragma unroll
            for (int ks = 0; ks < 4; ks++) {
                unsigned afr[2][4];
                ldsm_x4(afr[0], Ac + arowb[0] + cbx[ks]);
                ldsm_x4(afr[1], Ac + arowb[1] + cbx[ks]);
                unsigned bfr[2][4];
                ldsm_x4(bfr[0], Bc + browb[0] + cbx[ks]);
                ldsm_x4(bfr[1], Bc + browb[1] + cbx[ks]);
#pragma unroll
                for (int mf = 0; mf < 2; mf++)
#pragma unroll
                    for (int nf = 0; nf < 4; nf++)
                        mma_fp8h(acc[mf][nf], afr[mf],
                                 bfr[nf >> 1][nf & 1],
                                 bfr[nf >> 1][2 + (nf & 1)]);
            }
            cm++;
        }

        // ---- epilogue: f16x2 fma+ex2 (bias +15), f32 sums ----
        bool isdiag = (J == I);
        bool ispos  = (J == I + 32);

        if (isdiag | ispos) {
#pragma unroll
            for (int mf = 0; mf < 2; mf++)
#pragma unroll
                for (int h = 0; h < 2; h++) {
                    int rloc = warpM * 32 + mf * 16 + h * 8 + qrow;
                    int cc = rloc - warpN * 32;
                    if (cc >= 0 && cc < 32 && (((cc >> 1) & 3) == (lane & 3))) {
                        unsigned hp = acc[mf][cc >> 3][h];
                        if (isdiag) {
                            // identical f16 recompute -> bitwise-exact cancel
                            float2 fe = h2f2(h2ex2(hfma2u(hp, E2U, NC2U)));
                            rsum[mf][h] -= (cc & 1) ? fe.y : fe.x;
                        }
                        if (ispos) {
                            __half2 hv = *(__half2*)&hp;
                            float v = (cc & 1) ? __high2float(hv) : __low2float(hv);
                            g_pos[rowbase + rloc] = v * PSC;
                            g_pos[rowbase + rloc + BHALF] = v * PSC;
                        }
                    }
                }
        }

        float colp[8];
#pragma unroll
        for (int q = 0; q < 8; q++) colp[q] = 0.f;
#pragma unroll
        for (int mf = 0; mf < 2; mf++) {
            float slo = 0.f, shi = 0.f;
#pragma unroll
            for (int nf = 0; nf < 4; nf++) {
                unsigned eh0 = h2ex2(hfma2u(acc[mf][nf][0], E2U, NC2U));
                unsigned eh1 = h2ex2(hfma2u(acc[mf][nf][1], E2U, NC2U));
                float2 f01 = h2f2(eh0);
                float2 f23 = h2f2(eh1);
                slo += f01.x + f01.y;
                shi += f23.x + f23.y;
                colp[nf * 2]     += f01.x + f23.x;
                colp[nf * 2 + 1] += f01.y + f23.y;
            }
            rsum[mf][0] += slo;
            rsum[mf][1] += shi;
        }

        if (!isdiag) {
#pragma unroll
            for (int q = 0; q < 8; q++) {
                float v = colp[q];
                v += __shfl_xor_sync(0xFFFFFFFFu, v, 4);
                v += __shfl_xor_sync(0xFFFFFFFFu, v, 8);
                v += __shfl_xor_sync(0xFFFFFFFFu, v, 16);
                if (lane < 4) {
                    int ccol = (q >> 1) * 8 + 2 * lane + (q & 1);
                    atomicAdd(&g_rowsum[colbase + warpN * 32 + ccol], v);
                }
            }
        }
    }

    // final row flush
#pragma unroll
    for (int mf = 0; mf < 2; mf++)
#pragma unroll
        for (int h = 0; h < 2; h++) {
            float v = rsum[mf][h];
            v += __shfl_xor_sync(0xFFFFFFFFu, v, 1);
            v += __shfl_xor_sync(0xFFFFFFFFu, v, 2);
            if ((lane & 3) == 0 && curI >= 0)
                atomicAdd(&g_rowsum[(curI << 7) + warpM * 32 + mf * 16 + h * 8 + qrow], v);
        }

    // ========== phase 2: completion ticket -> loss + counter reset =========
    __threadfence();
    __syncthreads();
    __shared__ unsigned ticket;
    if (tid == 0) ticket = atomicAdd(&g_done, 1u);
    __syncthreads();
    if (ticket == NCTAS - 1) {
        float local_s = 0.f;
        for (int r = tid; r < NN; r += NTHR)
            local_s += (1.0f - g_pos[r]) * INV_TAU + __logf(g_rowsum[r]) - LOGC;
#pragma unroll
        for (int o = 16; o > 0; o >>= 1) local_s += __shfl_xor_sync(0xFFFFFFFFu, local_s, o);
        __shared__ float red[16];
        if (lane == 0) red[wid] = local_s;
        __syncthreads();
        if (tid < 16) {
            float v = red[tid];
#pragma unroll
            for (int o = 8; o > 0; o >>= 1) v += __shfl_xor_sync(0xFFFFu, v, o);
            if (tid == 0) {
                out[0] = v * (1.0f / (float)NN);
                g_bar  = 0u;                   // reset for next graph replay
                g_done = 0u;
                __threadfence();
            }
        }
    }
}

// ---------------------------------------------------------------------------
extern "C" void kernel_launch(void* const* d_in, const int* in_sizes, int n_in,
                              void* d_out, int out_size) {
    (void)in_sizes; (void)n_in; (void)out_size;
    const float* anchor   = (const float*)d_in[0];
    const float* positive = (const float*)d_in[1];

    cudaFuncSetAttribute(ntx_main, cudaFuncAttributeMaxDynamicSharedMemorySize,
                         SMEM_BYTES);

    ntx_main<<<NCTAS, NTHR, SMEM_BYTES>>>((float*)d_out, anchor, positive);
}